// round 14
// baseline (speedup 1.0000x reference)
#include <cuda_runtime.h>
#include <cstdint>

#define N_PIX 2304
#define HEADS 4
#define HD 16
#define CDIM 64
#define BATCH 2
#define BH 8
#define SPL 72            // N_PIX / 32 values per lane (warp-per-row)
#define SPL4 18           // N_PIX / 128 float4 loads per lane

// ---------------- scratch (static device globals; no allocation) -------------
__device__ float g_qkv1[BATCH*3*CDIM*N_PIX];          // after 1x1 conv, [b][ch][p]
__device__ float g_q[BH*N_PIX*HD];                    // [bh][j][d]
__device__ float g_k[BH*N_PIX*HD];
__device__ float g_v[BH*N_PIX*HD];
__device__ float g_logits[(size_t)BH*N_PIX*N_PIX];    // [rowg][col]  (170 MB)
__device__ float g_entrow[BH*N_PIX];                  // per-row entropy
__device__ float g_attnout[BATCH*CDIM*N_PIX];         // [b][c][p]

// monotone float<->uint order mapping (total order on finite floats)
__device__ __forceinline__ unsigned mapf(float f){
    unsigned u = __float_as_uint(f);
    return (u & 0x80000000u) ? ~u : (u | 0x80000000u);
}
__device__ __forceinline__ float unmapf(unsigned u){
    return __uint_as_float((u & 0x80000000u) ? (u & 0x7fffffffu) : ~u);
}

// ---------------- packed f32x2 helpers (sm_103a) ------------------------------
__device__ __forceinline__ unsigned long long fma2(unsigned long long a,
                                                   unsigned long long b,
                                                   unsigned long long c){
    unsigned long long d;
    asm("fma.rn.f32x2 %0, %1, %2, %3;" : "=l"(d) : "l"(a), "l"(b), "l"(c));
    return d;
}
__device__ __forceinline__ unsigned long long pack2(float lo, float hi){
    unsigned long long d;
    asm("mov.b64 %0, {%1, %2};" : "=l"(d) : "r"(__float_as_uint(lo)), "r"(__float_as_uint(hi)));
    return d;
}
__device__ __forceinline__ void unpack2(unsigned long long v, float& lo, float& hi){
    unsigned a, b;
    asm("mov.b64 {%0, %1}, %2;" : "=r"(a), "=r"(b) : "l"(v));
    lo = __uint_as_float(a); hi = __uint_as_float(b);
}

// ---------------- K1: 1x1 conv (x @ Wqkv + bqkv) -----------------------------
__global__ void k_qkv1(const float* __restrict__ x, const float* __restrict__ W,
                       const float* __restrict__ bias){
    int idx = blockIdx.x*blockDim.x + threadIdx.x;   // BATCH * 24 * N_PIX
    int p  = idx % N_PIX;
    int og = (idx / N_PIX) % 24;
    int b  = idx / (N_PIX*24);
    int o0 = og*8;
    const float* xb = x + b*CDIM*N_PIX + p;
    float acc[8];
    #pragma unroll
    for (int k=0;k<8;k++) acc[k] = bias[o0+k];
    #pragma unroll 8
    for (int c=0;c<CDIM;c++){
        float xv = xb[c*N_PIX];
        #pragma unroll
        for (int k=0;k<8;k++) acc[k] += W[(o0+k)*CDIM + c] * xv;
    }
    float* dst = g_qkv1 + b*3*CDIM*N_PIX + o0*N_PIX + p;
    #pragma unroll
    for (int k=0;k<8;k++) dst[k*N_PIX] = acc[k];
}

// ------- K2: 3x3 depthwise (SAME, zero pad, correlation) + head scatter ------
__global__ void k_pos(const float* __restrict__ Wpos, const float* __restrict__ bpos){
    int idx = blockIdx.x*blockDim.x + threadIdx.x;   // BATCH * 192 * N_PIX
    int p  = idx % N_PIX;
    int ch = (idx / N_PIX) % (3*CDIM);
    int b  = idx / (N_PIX*3*CDIM);
    int y = p / 48, xx = p % 48;
    const float* src = g_qkv1 + ((size_t)b*3*CDIM + ch)*N_PIX;
    const float* wp  = Wpos + ch*9;
    float acc = bpos[ch];
    #pragma unroll
    for (int dy=0; dy<3; dy++){
        int yy = y + dy - 1;
        if (yy < 0 || yy >= 48) continue;
        #pragma unroll
        for (int dx=0; dx<3; dx++){
            int xc = xx + dx - 1;
            if (xc < 0 || xc >= 48) continue;
            acc += src[yy*48 + xc] * wp[dy*3 + dx];
        }
    }
    int which = ch / CDIM;
    int cc    = ch % CDIM;
    int head  = cc / HD, d = cc % HD;
    int bh    = b*HEADS + head;
    float* dst = (which==0) ? g_q : (which==1) ? g_k : g_v;
    dst[((size_t)bh*N_PIX + p)*HD + d] = acc;
}

// ------- K3: QK^T logits (stored once) + per-row entropy, 4 rows/warp --------
// pass A dot products use packed fma.rn.f32x2 (half the fma-pipe issues).
__global__ __launch_bounds__(128,4) void k_ent(){
    int gw   = blockIdx.x*4 + (threadIdx.x >> 5);    // global warp id
    int lane = threadIdx.x & 31;
    int row0g = gw*4;                       // 4 rows per warp, never straddles bh
    int bh   = row0g / N_PIX;
    int row0 = row0g % N_PIX;

    const float* qb = g_q + ((size_t)bh*N_PIX + row0)*HD;
    unsigned long long qp[4][8];            // packed q pairs
    #pragma unroll
    for (int r=0;r<4;r++)
        #pragma unroll
        for (int d=0;d<8;d++)
            qp[r][d] = pack2(__ldg(qb + r*HD + 2*d), __ldg(qb + r*HD + 2*d + 1));

    const ulonglong2* kb2 = (const ulonglong2*)(g_k + (size_t)bh*N_PIX*HD);
    float* L0 = g_logits + (size_t)row0g*N_PIX;

    float mr[4] = {-1e30f,-1e30f,-1e30f,-1e30f};
    // pass A: logits + row max
    #pragma unroll 4
    for (int s=0; s<SPL; s++){
        int j = s*32 + lane;
        ulonglong2 ka = __ldg(kb2 + j*4 + 0);   // (k0,k1),(k2,k3)
        ulonglong2 kb_= __ldg(kb2 + j*4 + 1);   // (k4,k5),(k6,k7)
        ulonglong2 kc = __ldg(kb2 + j*4 + 2);
        ulonglong2 kd = __ldg(kb2 + j*4 + 3);
        #pragma unroll
        for (int r=0;r<4;r++){
            unsigned long long acc = fma2(qp[r][0], ka.x, 0ull);
            acc = fma2(qp[r][1], ka.y, acc);
            acc = fma2(qp[r][2], kb_.x, acc);
            acc = fma2(qp[r][3], kb_.y, acc);
            acc = fma2(qp[r][4], kc.x, acc);
            acc = fma2(qp[r][5], kc.y, acc);
            acc = fma2(qp[r][6], kd.x, acc);
            acc = fma2(qp[r][7], kd.y, acc);
            float lo, hi; unpack2(acc, lo, hi);
            float l = (lo + hi) * 0.25f;
            L0[(size_t)r*N_PIX + j] = l;
            mr[r] = fmaxf(mr[r], l);
        }
    }
    #pragma unroll
    for (int off=16; off; off>>=1)
        #pragma unroll
        for (int r=0;r<4;r++) mr[r] = fmaxf(mr[r], __shfl_xor_sync(0xffffffffu, mr[r], off));

    // pass B: reload logits via float4 (L2-hot), S and T with final max
    float S[4]={0,0,0,0}, T[4]={0,0,0,0};
    #pragma unroll 2
    for (int s4=0; s4<SPL4; s4++){
        #pragma unroll
        for (int r=0;r<4;r++){
            float4 l4 = __ldg((const float4*)(L0 + (size_t)r*N_PIX) + s4*32 + lane);
            float d0 = l4.x - mr[r]; float e0 = __expf(d0);
            float d1 = l4.y - mr[r]; float e1 = __expf(d1);
            float d2 = l4.z - mr[r]; float e2 = __expf(d2);
            float d3 = l4.w - mr[r]; float e3 = __expf(d3);
            S[r] += (e0+e1)+(e2+e3);
            T[r] += (d0*e0+d1*e1)+(d2*e2+d3*e3);
        }
    }
    #pragma unroll
    for (int off=16; off; off>>=1)
        #pragma unroll
        for (int r=0;r<4;r++){
            S[r] += __shfl_xor_sync(0xffffffffu, S[r], off);
            T[r] += __shfl_xor_sync(0xffffffffu, T[r], off);
        }
    if (lane < 4){
        float Sv = S[0], Tv = T[0];
        #pragma unroll
        for (int r=1;r<4;r++){ Sv = (lane==r)?S[r]:Sv; Tv = (lane==r)?T[r]:Tv; }
        g_entrow[row0g + lane] = logf(Sv) - Tv/Sv;
    }
}

// -------- K4: fused gate + exact kth threshold + cooperative P*V GEMM --------
__global__ __launch_bounds__(128,4) void k_sel(
        const float* __restrict__ Wg1, const float* __restrict__ bg1,
        const float* __restrict__ Wg2, const float* __restrict__ bg2){
    __shared__ __align__(16) float ws[4][N_PIX];     // weights, 36.9 KB
    __shared__ float part[4][4][16];                 // [srcwarp][row][d]
    __shared__ float invSs[4];
    __shared__ unsigned candbuf[4][64];
    __shared__ int s_keep;
    int lane = threadIdx.x & 31;
    int wip  = threadIdx.x >> 5;
    int gw   = blockIdx.x*4 + wip;                   // global row id
    int bh   = gw / N_PIX;                           // same for all 4 warps
    int row  = gw % N_PIX;
    int b = bh >> 2, h = bh & 3;

    // ---- fused gate (warp 0) -----------------------------------------------
    if (wip == 0){
        const float* er = g_entrow + bh*N_PIX;
        float s = 0.f;
        #pragma unroll
        for (int i=0;i<SPL;i++) s += er[i*32 + lane];
        #pragma unroll
        for (int off=16; off; off>>=1) s += __shfl_xor_sync(0xffffffffu, s, off);
        if (lane == 0){
            float e = s / (float)N_PIX;
            float dot = bg2[0];
            #pragma unroll
            for (int j=0;j<16;j++){
                float hg = fmaxf(0.f, e*Wg1[j] + bg1[j]);
                dot += hg * Wg2[j];
            }
            float ratio = 1.f/(1.f + expf(-dot)) * 0.9f + 0.1f;
            int kp = (int)ceilf(ratio * (float)N_PIX);
            s_keep = min(max(kp, 1), N_PIX);
        }
    }

    // ---- load row logits as float4 (element j = s4*128 + lane*4 + e) -------
    const float4* L4 = (const float4*)(g_logits + (size_t)gw*N_PIX);
    float F[SPL];
    float fmx = -1e30f, fmn = 1e30f;
    #pragma unroll
    for (int s4=0; s4<SPL4; s4++){
        float4 t = __ldg(L4 + s4*32 + lane);
        F[s4*4+0]=t.x; F[s4*4+1]=t.y; F[s4*4+2]=t.z; F[s4*4+3]=t.w;
        fmx = fmaxf(fmaxf(fmaxf(fmx,t.x),fmaxf(t.y,t.z)),t.w);
        fmn = fminf(fminf(fminf(fmn,t.x),fminf(t.y,t.z)),t.w);
    }
    #pragma unroll
    for (int off=16; off; off>>=1){
        fmx = fmaxf(fmx, __shfl_xor_sync(0xffffffffu, fmx, off));
        fmn = fminf(fmn, __shfl_xor_sync(0xffffffffu, fmn, off));
    }
    __syncthreads();
    int keep = s_keep;

    float fth;
    if (keep >= N_PIX){
        fth = fmn;
    } else {
        unsigned lo = mapf(fmn), hi = mapf(fmx);
        int cnt_lo  = N_PIX;   // count(>= lo)
        int cnt_hi1 = 0;       // count(>= hi+1)
        bool pinned = false;

        // phase 1: full-count bisection while candidate set is large
        while (lo < hi && (cnt_lo - cnt_hi1) > 64){
            unsigned mid = lo + ((hi - lo + 1u) >> 1);
            float fmid = unmapf(mid);
            float c0=0.f,c1=0.f,c2=0.f,c3=0.f;
            #pragma unroll
            for (int s=0; s<SPL; s+=4){
                c0 += (F[s]   >= fmid) ? 1.f : 0.f;
                c1 += (F[s+1] >= fmid) ? 1.f : 0.f;
                c2 += (F[s+2] >= fmid) ? 1.f : 0.f;
                c3 += (F[s+3] >= fmid) ? 1.f : 0.f;
            }
            int cnt = __reduce_add_sync(0xffffffffu, (int)((c0+c1)+(c2+c3)));
            if (cnt == keep){
                float mn = 1e30f;
                #pragma unroll
                for (int s=0; s<SPL; s++)
                    if (F[s] >= fmid) mn = fminf(mn, F[s]);
                #pragma unroll
                for (int off=16; off; off>>=1)
                    mn = fminf(mn, __shfl_xor_sync(0xffffffffu, mn, off));
                lo = mapf(mn);
                pinned = true;
                break;
            }
            if (cnt > keep){ lo = mid; cnt_lo = cnt; }
            else           { hi = mid - 1u; cnt_hi1 = cnt; }
        }

        // phase 2: compact candidates in [lo, hi] and finish on registers
        if (!pinned && lo < hi){
            float flo = unmapf(lo), fhi = unmapf(hi);
            int base = cnt_hi1;                 // count(> hi), fixed
            unsigned* buf = candbuf[wip];
            int nc = 0;
            #pragma unroll
            for (int s=0; s<SPL; s++){
                bool p = (F[s] >= flo) && (F[s] <= fhi);
                unsigned bal = __ballot_sync(0xffffffffu, p);
                if (p){
                    int pos = nc + __popc(bal & ((1u << lane) - 1u));
                    buf[pos] = __float_as_uint(F[s]);
                }
                nc += __popc(bal);
            }
            __syncwarp();
            const float NEG = __int_as_float(0xff800000);   // -inf sentinel
            float cA = (lane      < nc) ? __uint_as_float(buf[lane])      : NEG;
            float cB = (lane + 32 < nc) ? __uint_as_float(buf[lane + 32]) : NEG;
            while (lo < hi){
                unsigned mid = lo + ((hi - lo + 1u) >> 1);
                float fmid = unmapf(mid);
                int c = (cA >= fmid) + (cB >= fmid);
                int cnt = base + __reduce_add_sync(0xffffffffu, c);
                if (cnt >= keep) lo = mid; else hi = mid - 1u;
            }
        }
        fth = unmapf(lo);      // exact kth-largest logit
    }
    float m = fmx;

    // ---- weights -> smem, S -> invSs ---------------------------------------
    float S = 0.f;
    #pragma unroll
    for (int s4=0; s4<SPL4; s4++){
        float f0=F[s4*4+0], f1=F[s4*4+1], f2=F[s4*4+2], f3=F[s4*4+3];
        float w0=__expf(f0-m); w0 = (f0>=fth)?w0:0.f;
        float w1=__expf(f1-m); w1 = (f1>=fth)?w1:0.f;
        float w2=__expf(f2-m); w2 = (f2>=fth)?w2:0.f;
        float w3=__expf(f3-m); w3 = (f3>=fth)?w3:0.f;
        S += (w0+w1)+(w2+w3);
        *((float4*)&ws[wip][s4*128 + lane*4]) = make_float4(w0,w1,w2,w3);
    }
    #pragma unroll
    for (int off=16; off; off>>=1) S += __shfl_xor_sync(0xffffffffu, S, off);
    if (lane == 0) invSs[wip] = 1.f / S;
    __syncthreads();

    // ---- cooperative GEMM: out[4][16] = ws[4][2304] * V[2304][16] -----------
    // packed f32x2 FFMA in the loop; unpack to float4 BEFORE the (plain
    // float) shuffle reduction — no packed warp collectives.
    {
        int dg = lane & 3;          // d-component group (4 floats = 1 ulonglong2)
        int jo = lane >> 2;         // 0..7 consecutive j offset
        const ulonglong2* vrow2 = (const ulonglong2*)(g_v + (size_t)bh*N_PIX*HD);
        unsigned long long a0p=0ull,a0q=0ull,a1p=0ull,a1q=0ull,
                           a2p=0ull,a2q=0ull,a3p=0ull,a3q=0ull;
        int jb = wip*576 + jo;
        #pragma unroll 4
        for (int it=0; it<72; it++){
            int j = jb + it*8;
            ulonglong2 vp = __ldg(vrow2 + (size_t)j*4 + dg);  // (vx,vy),(vz,vw)
            unsigned long long wd0 = pack2(ws[0][j], ws[0][j]);
            unsigned long long wd1 = pack2(ws[1][j], ws[1][j]);
            unsigned long long wd2 = pack2(ws[2][j], ws[2][j]);
            unsigned long long wd3 = pack2(ws[3][j], ws[3][j]);
            a0p = fma2(wd0, vp.x, a0p); a0q = fma2(wd0, vp.y, a0q);
            a1p = fma2(wd1, vp.x, a1p); a1q = fma2(wd1, vp.y, a1q);
            a2p = fma2(wd2, vp.x, a2p); a2q = fma2(wd2, vp.y, a2q);
            a3p = fma2(wd3, vp.x, a3p); a3q = fma2(wd3, vp.y, a3q);
        }
        // unpack to plain floats, then the proven float shuffle reduction
        float4 a0, a1, a2, a3;
        unpack2(a0p, a0.x, a0.y); unpack2(a0q, a0.z, a0.w);
        unpack2(a1p, a1.x, a1.y); unpack2(a1q, a1.z, a1.w);
        unpack2(a2p, a2.x, a2.y); unpack2(a2q, a2.z, a2.w);
        unpack2(a3p, a3.x, a3.y); unpack2(a3q, a3.z, a3.w);
        #pragma unroll
        for (int off=4; off<32; off<<=1){
            a0.x += __shfl_xor_sync(0xffffffffu, a0.x, off);
            a0.y += __shfl_xor_sync(0xffffffffu, a0.y, off);
            a0.z += __shfl_xor_sync(0xffffffffu, a0.z, off);
            a0.w += __shfl_xor_sync(0xffffffffu, a0.w, off);
            a1.x += __shfl_xor_sync(0xffffffffu, a1.x, off);
            a1.y += __shfl_xor_sync(0xffffffffu, a1.y, off);
            a1.z += __shfl_xor_sync(0xffffffffu, a1.z, off);
            a1.w += __shfl_xor_sync(0xffffffffu, a1.w, off);
            a2.x += __shfl_xor_sync(0xffffffffu, a2.x, off);
            a2.y += __shfl_xor_sync(0xffffffffu, a2.y, off);
            a2.z += __shfl_xor_sync(0xffffffffu, a2.z, off);
            a2.w += __shfl_xor_sync(0xffffffffu, a2.w, off);
            a3.x += __shfl_xor_sync(0xffffffffu, a3.x, off);
            a3.y += __shfl_xor_sync(0xffffffffu, a3.y, off);
            a3.z += __shfl_xor_sync(0xffffffffu, a3.z, off);
            a3.w += __shfl_xor_sync(0xffffffffu, a3.w, off);
        }
        if (lane < 4){
            ((float4*)&part[wip][0][lane*4])[0] = a0;
            ((float4*)&part[wip][1][lane*4])[0] = a1;
            ((float4*)&part[wip][2][lane*4])[0] = a2;
            ((float4*)&part[wip][3][lane*4])[0] = a3;
        }
    }
    __syncthreads();

    // ---- final: warp r sums srcwarp partials, scales, stores ---------------
    if (lane < 16){
        float s = part[0][wip][lane] + part[1][wip][lane]
                + part[2][wip][lane] + part[3][wip][lane];
        float o = s * invSs[wip];
        g_attnout[((size_t)b*CDIM + h*HD + lane)*N_PIX + row] = o;
    }
}

// ---------------- K5: output projection --------------------------------------
__global__ void k_proj(const float* __restrict__ Wp, const float* __restrict__ bp,
                       float* __restrict__ out){
    int idx = blockIdx.x*blockDim.x + threadIdx.x;   // BATCH * 8 * N_PIX
    int p  = idx % N_PIX;
    int og = (idx / N_PIX) & 7;
    int b  = idx / (N_PIX*8);
    int o0 = og*8;
    const float* a = g_attnout + (size_t)b*CDIM*N_PIX + p;
    float acc[8];
    #pragma unroll
    for (int k=0;k<8;k++) acc[k] = bp[o0+k];
    #pragma unroll 8
    for (int c=0;c<CDIM;c++){
        float av = a[c*N_PIX];
        #pragma unroll
        for (int k=0;k<8;k++) acc[k] += Wp[(o0+k)*CDIM + c] * av;
    }
    float* dst = out + (size_t)b*CDIM*N_PIX + o0*N_PIX + p;
    #pragma unroll
    for (int k=0;k<8;k++) dst[k*N_PIX] = acc[k];
}

// ---------------- launch ------------------------------------------------------
extern "C" void kernel_launch(void* const* d_in, const int* in_sizes, int n_in,
                              void* d_out, int out_size){
    const float* x     = (const float*)d_in[0];
    const float* Wqkv  = (const float*)d_in[1];
    const float* bqkv  = (const float*)d_in[2];
    const float* Wpos  = (const float*)d_in[3];
    const float* bpos  = (const float*)d_in[4];
    const float* Wg1   = (const float*)d_in[5];
    const float* bg1   = (const float*)d_in[6];
    const float* Wg2   = (const float*)d_in[7];
    const float* bg2   = (const float*)d_in[8];
    const float* Wproj = (const float*)d_in[9];
    const float* bproj = (const float*)d_in[10];

    k_qkv1<<<432, 256>>>(x, Wqkv, bqkv);
    k_pos<<<3456, 256>>>(Wpos, bpos);
    k_ent<<<1152, 128>>>();                      // 4608 warps x 4 rows
    k_sel<<<4608, 128>>>(Wg1, bg1, Wg2, bg2);    // 4 rows per block, fused gate
    k_proj<<<144, 256>>>(Wproj, bproj, (float*)d_out);
}

// round 17
// speedup vs baseline: 1.0656x; 1.0656x over previous
#include <cuda_runtime.h>
#include <cstdint>

#define N_PIX 2304
#define HEADS 4
#define HD 16
#define CDIM 64
#define BATCH 2
#define BH 8
#define SPL 72            // N_PIX / 32 values per lane (warp-per-row)
#define SPL4 18           // N_PIX / 128 float4 loads per lane

// ---------------- scratch (static device globals; no allocation) -------------
__device__ float g_qkv1[BATCH*3*CDIM*N_PIX];          // after 1x1 conv, [b][ch][p]
__device__ float g_q[BH*N_PIX*HD];                    // [bh][j][d]
__device__ float g_k[BH*N_PIX*HD];
__device__ float g_v[BH*N_PIX*HD];
__device__ float g_logits[(size_t)BH*N_PIX*N_PIX];    // [rowg][col]  (170 MB)
__device__ float g_entrow[BH*N_PIX];                  // per-row entropy
__device__ float g_attnout[BATCH*CDIM*N_PIX];         // [b][c][p]

// monotone float<->uint order mapping (total order on finite floats)
__device__ __forceinline__ unsigned mapf(float f){
    unsigned u = __float_as_uint(f);
    return (u & 0x80000000u) ? ~u : (u | 0x80000000u);
}
__device__ __forceinline__ float unmapf(unsigned u){
    return __uint_as_float((u & 0x80000000u) ? (u & 0x7fffffffu) : ~u);
}

// ---------------- K1: 1x1 conv (x @ Wqkv + bqkv) -----------------------------
__global__ void k_qkv1(const float* __restrict__ x, const float* __restrict__ W,
                       const float* __restrict__ bias){
    int idx = blockIdx.x*blockDim.x + threadIdx.x;   // BATCH * 24 * N_PIX
    int p  = idx % N_PIX;
    int og = (idx / N_PIX) % 24;
    int b  = idx / (N_PIX*24);
    int o0 = og*8;
    const float* xb = x + b*CDIM*N_PIX + p;
    float acc[8];
    #pragma unroll
    for (int k=0;k<8;k++) acc[k] = bias[o0+k];
    #pragma unroll 8
    for (int c=0;c<CDIM;c++){
        float xv = xb[c*N_PIX];
        #pragma unroll
        for (int k=0;k<8;k++) acc[k] += W[(o0+k)*CDIM + c] * xv;
    }
    float* dst = g_qkv1 + b*3*CDIM*N_PIX + o0*N_PIX + p;
    #pragma unroll
    for (int k=0;k<8;k++) dst[k*N_PIX] = acc[k];
}

// ------- K2: 3x3 depthwise (SAME, zero pad, correlation) + head scatter ------
__global__ void k_pos(const float* __restrict__ Wpos, const float* __restrict__ bpos){
    int idx = blockIdx.x*blockDim.x + threadIdx.x;   // BATCH * 192 * N_PIX
    int p  = idx % N_PIX;
    int ch = (idx / N_PIX) % (3*CDIM);
    int b  = idx / (N_PIX*3*CDIM);
    int y = p / 48, xx = p % 48;
    const float* src = g_qkv1 + ((size_t)b*3*CDIM + ch)*N_PIX;
    const float* wp  = Wpos + ch*9;
    float acc = bpos[ch];
    #pragma unroll
    for (int dy=0; dy<3; dy++){
        int yy = y + dy - 1;
        if (yy < 0 || yy >= 48) continue;
        #pragma unroll
        for (int dx=0; dx<3; dx++){
            int xc = xx + dx - 1;
            if (xc < 0 || xc >= 48) continue;
            acc += src[yy*48 + xc] * wp[dy*3 + dx];
        }
    }
    int which = ch / CDIM;
    int cc    = ch % CDIM;
    int head  = cc / HD, d = cc % HD;
    int bh    = b*HEADS + head;
    float* dst = (which==0) ? g_q : (which==1) ? g_k : g_v;
    dst[((size_t)bh*N_PIX + p)*HD + d] = acc;
}

// ------- K3: QK^T logits (stored once) + single-pass entropy, 4 rows/warp ----
// No max subtraction: logits are O(1), so S0=sum(e^l), T0=sum(l e^l) are safe
// and H = log(S0) - T0/S0 is mathematically identical to the stabilized form.
__global__ __launch_bounds__(128,4) void k_ent(){
    int gw   = blockIdx.x*4 + (threadIdx.x >> 5);    // global warp id
    int lane = threadIdx.x & 31;
    int row0g = gw*4;                       // 4 rows per warp, never straddles bh
    int bh   = row0g / N_PIX;
    int row0 = row0g % N_PIX;

    const float* qb = g_q + ((size_t)bh*N_PIX + row0)*HD;
    float qr[4][HD];
    #pragma unroll
    for (int r=0;r<4;r++)
        #pragma unroll
        for (int d=0;d<HD;d++) qr[r][d] = __ldg(qb + r*HD + d);

    const float4* kb = (const float4*)(g_k + (size_t)bh*N_PIX*HD);
    float* L0 = g_logits + (size_t)row0g*N_PIX;

    float S[4]={0,0,0,0}, T[4]={0,0,0,0};
    #pragma unroll 4
    for (int s=0; s<SPL; s++){
        int j = s*32 + lane;
        float4 k0 = __ldg(kb + j*4 + 0);
        float4 k1 = __ldg(kb + j*4 + 1);
        float4 k2 = __ldg(kb + j*4 + 2);
        float4 k3 = __ldg(kb + j*4 + 3);
        #pragma unroll
        for (int r=0;r<4;r++){
            float a = qr[r][0]*k0.x + qr[r][1]*k0.y + qr[r][2]*k0.z + qr[r][3]*k0.w;
            float b2= qr[r][4]*k1.x + qr[r][5]*k1.y + qr[r][6]*k1.z + qr[r][7]*k1.w;
            float c = qr[r][8]*k2.x + qr[r][9]*k2.y + qr[r][10]*k2.z+ qr[r][11]*k2.w;
            float d = qr[r][12]*k3.x+ qr[r][13]*k3.y+ qr[r][14]*k3.z+ qr[r][15]*k3.w;
            float l = (a+b2+c+d) * 0.25f;
            L0[(size_t)r*N_PIX + j] = l;
            float e = __expf(l);
            S[r] += e;
            T[r] = fmaf(l, e, T[r]);
        }
    }
    #pragma unroll
    for (int off=16; off; off>>=1)
        #pragma unroll
        for (int r=0;r<4;r++){
            S[r] += __shfl_xor_sync(0xffffffffu, S[r], off);
            T[r] += __shfl_xor_sync(0xffffffffu, T[r], off);
        }
    if (lane < 4){
        float Sv = S[0], Tv = T[0];
        #pragma unroll
        for (int r=1;r<4;r++){ Sv = (lane==r)?S[r]:Sv; Tv = (lane==r)?T[r]:Tv; }
        g_entrow[row0g + lane] = logf(Sv) - Tv/Sv;
    }
}

// -------- K4: fused gate + exact kth threshold + cooperative P*V GEMM --------
__global__ __launch_bounds__(128,4) void k_sel(
        const float* __restrict__ Wg1, const float* __restrict__ bg1,
        const float* __restrict__ Wg2, const float* __restrict__ bg2){
    __shared__ __align__(16) float ws[4][N_PIX];     // weights, 36.9 KB
    __shared__ float part[4][4][16];                 // [srcwarp][row][d]
    __shared__ float invSs[4];
    __shared__ unsigned candbuf[4][64];
    __shared__ int s_keep;
    int lane = threadIdx.x & 31;
    int wip  = threadIdx.x >> 5;
    int gw   = blockIdx.x*4 + wip;                   // global row id
    int bh   = gw / N_PIX;                           // same for all 4 warps
    int row  = gw % N_PIX;
    int b = bh >> 2, h = bh & 3;

    // ---- fused gate (warp 0) -----------------------------------------------
    if (wip == 0){
        const float* er = g_entrow + bh*N_PIX;
        float s = 0.f;
        #pragma unroll
        for (int i=0;i<SPL;i++) s += er[i*32 + lane];
        #pragma unroll
        for (int off=16; off; off>>=1) s += __shfl_xor_sync(0xffffffffu, s, off);
        if (lane == 0){
            float e = s / (float)N_PIX;
            float dot = bg2[0];
            #pragma unroll
            for (int j=0;j<16;j++){
                float hg = fmaxf(0.f, e*Wg1[j] + bg1[j]);
                dot += hg * Wg2[j];
            }
            float ratio = 1.f/(1.f + expf(-dot)) * 0.9f + 0.1f;
            int kp = (int)ceilf(ratio * (float)N_PIX);
            s_keep = min(max(kp, 1), N_PIX);
        }
    }

    // ---- load row logits as float4 (element j = s4*128 + lane*4 + e) -------
    const float4* L4 = (const float4*)(g_logits + (size_t)gw*N_PIX);
    float F[SPL];
    float fmx = -1e30f, fmn = 1e30f;
    #pragma unroll
    for (int s4=0; s4<SPL4; s4++){
        float4 t = __ldg(L4 + s4*32 + lane);
        F[s4*4+0]=t.x; F[s4*4+1]=t.y; F[s4*4+2]=t.z; F[s4*4+3]=t.w;
        fmx = fmaxf(fmaxf(fmaxf(fmx,t.x),fmaxf(t.y,t.z)),t.w);
        fmn = fminf(fminf(fminf(fmn,t.x),fminf(t.y,t.z)),t.w);
    }
    #pragma unroll
    for (int off=16; off; off>>=1){
        fmx = fmaxf(fmx, __shfl_xor_sync(0xffffffffu, fmx, off));
        fmn = fminf(fmn, __shfl_xor_sync(0xffffffffu, fmn, off));
    }
    __syncthreads();
    int keep = s_keep;

    float fth;
    if (keep >= N_PIX){
        fth = fmn;
    } else {
        unsigned lo = mapf(fmn), hi = mapf(fmx);
        int cnt_lo  = N_PIX;   // count(>= lo)
        int cnt_hi1 = 0;       // count(>= hi+1)
        bool pinned = false;

        // phase 1: full-count bisection while candidate set is large
        while (lo < hi && (cnt_lo - cnt_hi1) > 64){
            unsigned mid = lo + ((hi - lo + 1u) >> 1);
            float fmid = unmapf(mid);
            float c0=0.f,c1=0.f,c2=0.f,c3=0.f;
            #pragma unroll
            for (int s=0; s<SPL; s+=4){
                c0 += (F[s]   >= fmid) ? 1.f : 0.f;
                c1 += (F[s+1] >= fmid) ? 1.f : 0.f;
                c2 += (F[s+2] >= fmid) ? 1.f : 0.f;
                c3 += (F[s+3] >= fmid) ? 1.f : 0.f;
            }
            int cnt = __reduce_add_sync(0xffffffffu, (int)((c0+c1)+(c2+c3)));
            if (cnt == keep){
                float mn = 1e30f;
                #pragma unroll
                for (int s=0; s<SPL; s++)
                    if (F[s] >= fmid) mn = fminf(mn, F[s]);
                #pragma unroll
                for (int off=16; off; off>>=1)
                    mn = fminf(mn, __shfl_xor_sync(0xffffffffu, mn, off));
                lo = mapf(mn);
                pinned = true;
                break;
            }
            if (cnt > keep){ lo = mid; cnt_lo = cnt; }
            else           { hi = mid - 1u; cnt_hi1 = cnt; }
        }

        // phase 2: compact candidates in [lo, hi] and finish on registers
        if (!pinned && lo < hi){
            float flo = unmapf(lo), fhi = unmapf(hi);
            int base = cnt_hi1;                 // count(> hi), fixed
            unsigned* buf = candbuf[wip];
            int nc = 0;
            #pragma unroll
            for (int s=0; s<SPL; s++){
                bool p = (F[s] >= flo) && (F[s] <= fhi);
                unsigned bal = __ballot_sync(0xffffffffu, p);
                if (p){
                    int pos = nc + __popc(bal & ((1u << lane) - 1u));
                    buf[pos] = __float_as_uint(F[s]);
                }
                nc += __popc(bal);
            }
            __syncwarp();
            const float NEG = __int_as_float(0xff800000);   // -inf sentinel
            float cA = (lane      < nc) ? __uint_as_float(buf[lane])      : NEG;
            float cB = (lane + 32 < nc) ? __uint_as_float(buf[lane + 32]) : NEG;
            while (lo < hi){
                unsigned mid = lo + ((hi - lo + 1u) >> 1);
                float fmid = unmapf(mid);
                int c = (cA >= fmid) + (cB >= fmid);
                int cnt = base + __reduce_add_sync(0xffffffffu, c);
                if (cnt >= keep) lo = mid; else hi = mid - 1u;
            }
        }
        fth = unmapf(lo);      // exact kth-largest logit
    }
    float m = fmx;

    // ---- weights -> smem, S -> invSs ---------------------------------------
    float S = 0.f;
    #pragma unroll
    for (int s4=0; s4<SPL4; s4++){
        float f0=F[s4*4+0], f1=F[s4*4+1], f2=F[s4*4+2], f3=F[s4*4+3];
        float w0=__expf(f0-m); w0 = (f0>=fth)?w0:0.f;
        float w1=__expf(f1-m); w1 = (f1>=fth)?w1:0.f;
        float w2=__expf(f2-m); w2 = (f2>=fth)?w2:0.f;
        float w3=__expf(f3-m); w3 = (f3>=fth)?w3:0.f;
        S += (w0+w1)+(w2+w3);
        *((float4*)&ws[wip][s4*128 + lane*4]) = make_float4(w0,w1,w2,w3);
    }
    #pragma unroll
    for (int off=16; off; off>>=1) S += __shfl_xor_sync(0xffffffffu, S, off);
    if (lane == 0) invSs[wip] = 1.f / S;
    __syncthreads();

    // ---- cooperative GEMM: out[4][16] = ws[4][2304] * V[2304][16] -----------
    {
        int dg = lane & 3;          // d-component group (4 floats)
        int jo = lane >> 2;         // 0..7 consecutive j offset
        const float4* vrow = (const float4*)(g_v + (size_t)bh*N_PIX*HD);
        float4 a0 = {0,0,0,0}, a1 = {0,0,0,0}, a2 = {0,0,0,0}, a3 = {0,0,0,0};
        int jb = wip*576 + jo;
        #pragma unroll 4
        for (int it=0; it<72; it++){
            int j = jb + it*8;
            float4 v = vrow[j*4 + dg];
            float w0 = ws[0][j], w1 = ws[1][j], w2 = ws[2][j], w3 = ws[3][j];
            a0.x += w0*v.x; a0.y += w0*v.y; a0.z += w0*v.z; a0.w += w0*v.w;
            a1.x += w1*v.x; a1.y += w1*v.y; a1.z += w1*v.z; a1.w += w1*v.w;
            a2.x += w2*v.x; a2.y += w2*v.y; a2.z += w2*v.z; a2.w += w2*v.w;
            a3.x += w3*v.x; a3.y += w3*v.y; a3.z += w3*v.z; a3.w += w3*v.w;
        }
        // reduce across jo (lanes differing in bits 2..4)
        #pragma unroll
        for (int off=4; off<32; off<<=1){
            a0.x += __shfl_xor_sync(0xffffffffu, a0.x, off);
            a0.y += __shfl_xor_sync(0xffffffffu, a0.y, off);
            a0.z += __shfl_xor_sync(0xffffffffu, a0.z, off);
            a0.w += __shfl_xor_sync(0xffffffffu, a0.w, off);
            a1.x += __shfl_xor_sync(0xffffffffu, a1.x, off);
            a1.y += __shfl_xor_sync(0xffffffffu, a1.y, off);
            a1.z += __shfl_xor_sync(0xffffffffu, a1.z, off);
            a1.w += __shfl_xor_sync(0xffffffffu, a1.w, off);
            a2.x += __shfl_xor_sync(0xffffffffu, a2.x, off);
            a2.y += __shfl_xor_sync(0xffffffffu, a2.y, off);
            a2.z += __shfl_xor_sync(0xffffffffu, a2.z, off);
            a2.w += __shfl_xor_sync(0xffffffffu, a2.w, off);
            a3.x += __shfl_xor_sync(0xffffffffu, a3.x, off);
            a3.y += __shfl_xor_sync(0xffffffffu, a3.y, off);
            a3.z += __shfl_xor_sync(0xffffffffu, a3.z, off);
            a3.w += __shfl_xor_sync(0xffffffffu, a3.w, off);
        }
        if (lane < 4){
            ((float4*)&part[wip][0][lane*4])[0] = a0;
            ((float4*)&part[wip][1][lane*4])[0] = a1;
            ((float4*)&part[wip][2][lane*4])[0] = a2;
            ((float4*)&part[wip][3][lane*4])[0] = a3;
        }
    }
    __syncthreads();

    // ---- final: warp r sums srcwarp partials, scales, stores ---------------
    if (lane < 16){
        float s = part[0][wip][lane] + part[1][wip][lane]
                + part[2][wip][lane] + part[3][wip][lane];
        float o = s * invSs[wip];
        g_attnout[((size_t)b*CDIM + h*HD + lane)*N_PIX + row] = o;
    }
}

// ---------------- K5: output projection --------------------------------------
__global__ void k_proj(const float* __restrict__ Wp, const float* __restrict__ bp,
                       float* __restrict__ out){
    int idx = blockIdx.x*blockDim.x + threadIdx.x;   // BATCH * 8 * N_PIX
    int p  = idx % N_PIX;
    int og = (idx / N_PIX) & 7;
    int b  = idx / (N_PIX*8);
    int o0 = og*8;
    const float* a = g_attnout + (size_t)b*CDIM*N_PIX + p;
    float acc[8];
    #pragma unroll
    for (int k=0;k<8;k++) acc[k] = bp[o0+k];
    #pragma unroll 8
    for (int c=0;c<CDIM;c++){
        float av = a[c*N_PIX];
        #pragma unroll
        for (int k=0;k<8;k++) acc[k] += Wp[(o0+k)*CDIM + c] * av;
    }
    float* dst = out + (size_t)b*CDIM*N_PIX + o0*N_PIX + p;
    #pragma unroll
    for (int k=0;k<8;k++) dst[k*N_PIX] = acc[k];
}

// ---------------- launch ------------------------------------------------------
extern "C" void kernel_launch(void* const* d_in, const int* in_sizes, int n_in,
                              void* d_out, int out_size){
    const float* x     = (const float*)d_in[0];
    const float* Wqkv  = (const float*)d_in[1];
    const float* bqkv  = (const float*)d_in[2];
    const float* Wpos  = (const float*)d_in[3];
    const float* bpos  = (const float*)d_in[4];
    const float* Wg1   = (const float*)d_in[5];
    const float* bg1   = (const float*)d_in[6];
    const float* Wg2   = (const float*)d_in[7];
    const float* bg2   = (const float*)d_in[8];
    const float* Wproj = (const float*)d_in[9];
    const float* bproj = (const float*)d_in[10];

    k_qkv1<<<432, 256>>>(x, Wqkv, bqkv);
    k_pos<<<3456, 256>>>(Wpos, bpos);
    k_ent<<<1152, 128>>>();                      // 4608 warps x 4 rows
    k_sel<<<4608, 128>>>(Wg1, bg1, Wg2, bg2);    // 4 rows per block, fused gate
    k_proj<<<144, 256>>>(Wproj, bproj, (float*)d_out);
}